// round 2
// baseline (speedup 1.0000x reference)
#include <cuda_runtime.h>

// Problem constants
#define NPTS 4096            // spatial points (16*16*16)
#define NQ   8192            // attention rows = NPTS * HEADS
#define CIN  64
#define CK   32              // qkv channels (= CV)
#define DK   16              // head dim (= dv)
#define COUT 64

// Attention tiling
#define KCHUNKS 64           // key-dimension splits
#define KC      128          // keys per chunk (KCHUNKS*KC = NQ)
#define QBLOCK  512          // queries per CTA (256 threads x 2 queries)

// Scratch (static device arrays; no allocation in kernel_launch)
__device__ float g_q[NQ * DK];            // pre-scaled by dk^-0.5 * log2(e)
__device__ float g_k[NQ * DK];
__device__ float g_v[NQ * DK];
__device__ float g_accp[KCHUNKS * NQ * DK];  // partial sum(exp * v)
__device__ float g_lp[KCHUNKS * NQ];         // partial sum(exp)

__device__ __forceinline__ float fast_exp2(float x) {
    float y;
    asm("ex2.approx.ftz.f32 %0, %1;" : "=f"(y) : "f"(x));
    return y;
}

// ---------------------------------------------------------------------------
// Kernel 1: QKV 1x1x1 conv projections.  One thread per spatial point.
// q[p][o] = sum_c x[c][p] * qw[o][c] + qb[o]   (o in [0,32)), same for k,v.
// Row layout: flattened [NQ][DK] == [NPTS][CK] (heads interleave naturally).
// Q is pre-scaled by dk^-0.5 * log2(e) so the attention loop uses ex2 directly.
// ---------------------------------------------------------------------------
__global__ __launch_bounds__(256) void proj_kernel(
    const float* __restrict__ x,
    const float* __restrict__ qw, const float* __restrict__ qb,
    const float* __restrict__ kw, const float* __restrict__ kb,
    const float* __restrict__ vw, const float* __restrict__ vb)
{
    __shared__ float4 wq[CK * 16], wk[CK * 16], wv[CK * 16];  // 32x64 floats each
    const int tid = threadIdx.x;
    for (int i = tid; i < CK * 16; i += 256) {
        wq[i] = ((const float4*)qw)[i];
        wk[i] = ((const float4*)kw)[i];
        wv[i] = ((const float4*)vw)[i];
    }
    __syncthreads();

    const int p = blockIdx.x * 256 + tid;

    float xr[CIN];
    #pragma unroll
    for (int c = 0; c < CIN; c++) xr[c] = __ldg(&x[c * NPTS + p]);

    const float QS = 0.25f * 1.4426950408889634f;  // dk^-0.5 * log2(e)

    for (int o = 0; o < CK; o++) {
        float aq = __ldg(&qb[o]);
        float ak = __ldg(&kb[o]);
        float av = __ldg(&vb[o]);
        #pragma unroll
        for (int c4 = 0; c4 < 16; c4++) {
            float4 a = wq[o * 16 + c4];
            aq = fmaf(a.x, xr[4 * c4 + 0], aq);
            aq = fmaf(a.y, xr[4 * c4 + 1], aq);
            aq = fmaf(a.z, xr[4 * c4 + 2], aq);
            aq = fmaf(a.w, xr[4 * c4 + 3], aq);
            float4 b = wk[o * 16 + c4];
            ak = fmaf(b.x, xr[4 * c4 + 0], ak);
            ak = fmaf(b.y, xr[4 * c4 + 1], ak);
            ak = fmaf(b.z, xr[4 * c4 + 2], ak);
            ak = fmaf(b.w, xr[4 * c4 + 3], ak);
            float4 cc = wv[o * 16 + c4];
            av = fmaf(cc.x, xr[4 * c4 + 0], av);
            av = fmaf(cc.y, xr[4 * c4 + 1], av);
            av = fmaf(cc.z, xr[4 * c4 + 2], av);
            av = fmaf(cc.w, xr[4 * c4 + 3], av);
        }
        g_q[p * CK + o] = aq * QS;
        g_k[p * CK + o] = ak;
        g_v[p * CK + o] = av;
    }
}

// ---------------------------------------------------------------------------
// Kernel 2: attention partials.  grid = (NQ/QBLOCK, KCHUNKS).
// Each thread owns 2 queries (registers: q[16]x2, acc[16]x2, l x2) and walks
// its CTA's key chunk.  No max-subtraction (logits are O(1), fp32-safe), so
// partials across chunks combine by plain addition -> deterministic.
// K/V rows are uniform-address loads (warp broadcast), amortized over 2 queries.
// ---------------------------------------------------------------------------
__global__ __launch_bounds__(256, 2) void attn_kernel()
{
    const int tid = threadIdx.x;
    const int q0 = blockIdx.x * QBLOCK + tid;
    const int q1 = q0 + 256;
    const int kbase = blockIdx.y * KC;

    float qA[16], qB[16];
    {
        const float4* qp0 = (const float4*)(g_q + q0 * DK);
        const float4* qp1 = (const float4*)(g_q + q1 * DK);
        #pragma unroll
        for (int i = 0; i < 4; i++) {
            float4 t = qp0[i];
            qA[4 * i + 0] = t.x; qA[4 * i + 1] = t.y; qA[4 * i + 2] = t.z; qA[4 * i + 3] = t.w;
            float4 u = qp1[i];
            qB[4 * i + 0] = u.x; qB[4 * i + 1] = u.y; qB[4 * i + 2] = u.z; qB[4 * i + 3] = u.w;
        }
    }

    float accA[16], accB[16];
    #pragma unroll
    for (int i = 0; i < 16; i++) { accA[i] = 0.f; accB[i] = 0.f; }
    float lA = 0.f, lB = 0.f;

    const float4* kp = (const float4*)(g_k + kbase * DK);
    const float4* vp = (const float4*)(g_v + kbase * DK);

    #pragma unroll 2
    for (int j = 0; j < KC; j++) {
        float kr[16];
        {
            float4 t0 = __ldg(kp + 4 * j + 0);
            float4 t1 = __ldg(kp + 4 * j + 1);
            float4 t2 = __ldg(kp + 4 * j + 2);
            float4 t3 = __ldg(kp + 4 * j + 3);
            kr[0] = t0.x; kr[1] = t0.y; kr[2]  = t0.z; kr[3]  = t0.w;
            kr[4] = t1.x; kr[5] = t1.y; kr[6]  = t1.z; kr[7]  = t1.w;
            kr[8] = t2.x; kr[9] = t2.y; kr[10] = t2.z; kr[11] = t2.w;
            kr[12] = t3.x; kr[13] = t3.y; kr[14] = t3.z; kr[15] = t3.w;
        }
        // two partial chains per query to shorten the dependency chain
        float dA0 = 0.f, dA1 = 0.f, dB0 = 0.f, dB1 = 0.f;
        #pragma unroll
        for (int c = 0; c < 8; c++) {
            dA0 = fmaf(qA[c], kr[c], dA0);
            dA1 = fmaf(qA[c + 8], kr[c + 8], dA1);
            dB0 = fmaf(qB[c], kr[c], dB0);
            dB1 = fmaf(qB[c + 8], kr[c + 8], dB1);
        }
        float pA = fast_exp2(dA0 + dA1);
        float pB = fast_exp2(dB0 + dB1);
        lA += pA;
        lB += pB;

        float vr[16];
        {
            float4 t0 = __ldg(vp + 4 * j + 0);
            float4 t1 = __ldg(vp + 4 * j + 1);
            float4 t2 = __ldg(vp + 4 * j + 2);
            float4 t3 = __ldg(vp + 4 * j + 3);
            vr[0] = t0.x; vr[1] = t0.y; vr[2]  = t0.z; vr[3]  = t0.w;
            vr[4] = t1.x; vr[5] = t1.y; vr[6]  = t1.z; vr[7]  = t1.w;
            vr[8] = t2.x; vr[9] = t2.y; vr[10] = t2.z; vr[11] = t2.w;
            vr[12] = t3.x; vr[13] = t3.y; vr[14] = t3.z; vr[15] = t3.w;
        }
        #pragma unroll
        for (int c = 0; c < 16; c++) {
            accA[c] = fmaf(pA, vr[c], accA[c]);
            accB[c] = fmaf(pB, vr[c], accB[c]);
        }
    }

    g_lp[blockIdx.y * NQ + q0] = lA;
    g_lp[blockIdx.y * NQ + q1] = lB;
    float4* ap0 = (float4*)(g_accp + (blockIdx.y * NQ + q0) * DK);
    float4* ap1 = (float4*)(g_accp + (blockIdx.y * NQ + q1) * DK);
    #pragma unroll
    for (int i = 0; i < 4; i++) {
        ap0[i] = make_float4(accA[4 * i], accA[4 * i + 1], accA[4 * i + 2], accA[4 * i + 3]);
        ap1[i] = make_float4(accB[4 * i], accB[4 * i + 1], accB[4 * i + 2], accB[4 * i + 3]);
    }
}

// ---------------------------------------------------------------------------
// Kernel 3: reduce partials across chunks, normalize, merge heads, and apply
// the 1x1x1 output projection.  One thread per spatial point.
// y[o][p] = ob[o] + sum_c ow[o][c] * (acc[q(c)][c%16] / l[q(c)])
// ---------------------------------------------------------------------------
__global__ __launch_bounds__(256) void out_kernel(
    const float* __restrict__ ow, const float* __restrict__ ob,
    float* __restrict__ y)
{
    __shared__ float4 wsm[COUT * 8];  // 64x32 floats
    const int tid = threadIdx.x;
    for (int i = tid; i < COUT * 8; i += 256) wsm[i] = ((const float4*)ow)[i];
    __syncthreads();

    const int p = blockIdx.x * 256 + tid;
    const int q0 = 2 * p, q1 = 2 * p + 1;

    float a0[16], a1[16];
    float l0 = 0.f, l1 = 0.f;
    #pragma unroll
    for (int i = 0; i < 16; i++) { a0[i] = 0.f; a1[i] = 0.f; }

    for (int ch = 0; ch < KCHUNKS; ch++) {
        l0 += g_lp[ch * NQ + q0];
        l1 += g_lp[ch * NQ + q1];
        const float4* ap0 = (const float4*)(g_accp + (ch * NQ + q0) * DK);
        const float4* ap1 = (const float4*)(g_accp + (ch * NQ + q1) * DK);
        #pragma unroll
        for (int i = 0; i < 4; i++) {
            float4 t = ap0[i];
            a0[4 * i + 0] += t.x; a0[4 * i + 1] += t.y;
            a0[4 * i + 2] += t.z; a0[4 * i + 3] += t.w;
            float4 u = ap1[i];
            a1[4 * i + 0] += u.x; a1[4 * i + 1] += u.y;
            a1[4 * i + 2] += u.z; a1[4 * i + 3] += u.w;
        }
    }

    const float inv0 = 1.0f / l0;
    const float inv1 = 1.0f / l1;
    float o32[32];
    #pragma unroll
    for (int i = 0; i < 16; i++) {
        o32[i] = a0[i] * inv0;        // head 0 -> channels [0,16)
        o32[16 + i] = a1[i] * inv1;   // head 1 -> channels [16,32)
    }

    for (int o = 0; o < COUT; o++) {
        float acc = __ldg(&ob[o]);
        #pragma unroll
        for (int c4 = 0; c4 < 8; c4++) {
            float4 w = wsm[o * 8 + c4];
            acc = fmaf(w.x, o32[4 * c4 + 0], acc);
            acc = fmaf(w.y, o32[4 * c4 + 1], acc);
            acc = fmaf(w.z, o32[4 * c4 + 2], acc);
            acc = fmaf(w.w, o32[4 * c4 + 3], acc);
        }
        y[o * NPTS + p] = acc;
    }
}

// ---------------------------------------------------------------------------
extern "C" void kernel_launch(void* const* d_in, const int* in_sizes, int n_in,
                              void* d_out, int out_size)
{
    const float* x  = (const float*)d_in[0];
    const float* qw = (const float*)d_in[1];
    const float* qb = (const float*)d_in[2];
    const float* kw = (const float*)d_in[3];
    const float* kb = (const float*)d_in[4];
    const float* vw = (const float*)d_in[5];
    const float* vb = (const float*)d_in[6];
    const float* ow = (const float*)d_in[7];
    const float* ob = (const float*)d_in[8];
    float* y = (float*)d_out;

    proj_kernel<<<NPTS / 256, 256>>>(x, qw, qb, kw, kb, vw, vb);
    dim3 grid(NQ / QBLOCK, KCHUNKS);
    attn_kernel<<<grid, 256>>>();
    out_kernel<<<NPTS / 256, 256>>>(ow, ob, y);
}

// round 3
// speedup vs baseline: 1.0004x; 1.0004x over previous
#include <cuda_runtime.h>

// Problem constants
#define NPTS 4096            // spatial points (16*16*16)
#define NQ   8192            // attention rows = NPTS * HEADS
#define CIN  64
#define CK   32              // qkv channels (= CV)
#define DK   16              // head dim (= dv)
#define COUT 64

// Attention tiling
#define KCHUNKS 64           // key-dimension splits
#define KC      128          // keys per chunk (KCHUNKS*KC = NQ)
#define QBLOCK  512          // queries per CTA (256 threads x 2 queries)

// Scratch (static device arrays; no allocation in kernel_launch)
__device__ float g_q[NQ * DK];            // pre-scaled by dk^-0.5 * log2(e)
__device__ float g_k[NQ * DK];
__device__ float g_v[NQ * DK];
__device__ float g_accp[KCHUNKS * NQ * DK];  // partial sum(exp * v)
__device__ float g_lp[KCHUNKS * NQ];         // partial sum(exp)

__device__ __forceinline__ float fast_exp2(float x) {
    float y;
    asm("ex2.approx.ftz.f32 %0, %1;" : "=f"(y) : "f"(x));
    return y;
}

// ---------------------------------------------------------------------------
// Kernel 1: QKV 1x1x1 conv projections.  One thread per spatial point.
// q[p][o] = sum_c x[c][p] * qw[o][c] + qb[o]   (o in [0,32)), same for k,v.
// Row layout: flattened [NQ][DK] == [NPTS][CK] (heads interleave naturally).
// Q is pre-scaled by dk^-0.5 * log2(e) so the attention loop uses ex2 directly.
// ---------------------------------------------------------------------------
__global__ __launch_bounds__(256) void proj_kernel(
    const float* __restrict__ x,
    const float* __restrict__ qw, const float* __restrict__ qb,
    const float* __restrict__ kw, const float* __restrict__ kb,
    const float* __restrict__ vw, const float* __restrict__ vb)
{
    __shared__ float4 wq[CK * 16], wk[CK * 16], wv[CK * 16];  // 32x64 floats each
    const int tid = threadIdx.x;
    for (int i = tid; i < CK * 16; i += 256) {
        wq[i] = ((const float4*)qw)[i];
        wk[i] = ((const float4*)kw)[i];
        wv[i] = ((const float4*)vw)[i];
    }
    __syncthreads();

    const int p = blockIdx.x * 256 + tid;

    float xr[CIN];
    #pragma unroll
    for (int c = 0; c < CIN; c++) xr[c] = __ldg(&x[c * NPTS + p]);

    const float QS = 0.25f * 1.4426950408889634f;  // dk^-0.5 * log2(e)

    for (int o = 0; o < CK; o++) {
        float aq = __ldg(&qb[o]);
        float ak = __ldg(&kb[o]);
        float av = __ldg(&vb[o]);
        #pragma unroll
        for (int c4 = 0; c4 < 16; c4++) {
            float4 a = wq[o * 16 + c4];
            aq = fmaf(a.x, xr[4 * c4 + 0], aq);
            aq = fmaf(a.y, xr[4 * c4 + 1], aq);
            aq = fmaf(a.z, xr[4 * c4 + 2], aq);
            aq = fmaf(a.w, xr[4 * c4 + 3], aq);
            float4 b = wk[o * 16 + c4];
            ak = fmaf(b.x, xr[4 * c4 + 0], ak);
            ak = fmaf(b.y, xr[4 * c4 + 1], ak);
            ak = fmaf(b.z, xr[4 * c4 + 2], ak);
            ak = fmaf(b.w, xr[4 * c4 + 3], ak);
            float4 cc = wv[o * 16 + c4];
            av = fmaf(cc.x, xr[4 * c4 + 0], av);
            av = fmaf(cc.y, xr[4 * c4 + 1], av);
            av = fmaf(cc.z, xr[4 * c4 + 2], av);
            av = fmaf(cc.w, xr[4 * c4 + 3], av);
        }
        g_q[p * CK + o] = aq * QS;
        g_k[p * CK + o] = ak;
        g_v[p * CK + o] = av;
    }
}

// ---------------------------------------------------------------------------
// Kernel 2: attention partials.  grid = (NQ/QBLOCK, KCHUNKS).
// Each thread owns 2 queries (registers: q[16]x2, acc[16]x2, l x2) and walks
// its CTA's key chunk.  No max-subtraction (logits are O(1), fp32-safe), so
// partials across chunks combine by plain addition -> deterministic.
// K/V rows are uniform-address loads (warp broadcast), amortized over 2 queries.
// ---------------------------------------------------------------------------
__global__ __launch_bounds__(256, 2) void attn_kernel()
{
    const int tid = threadIdx.x;
    const int q0 = blockIdx.x * QBLOCK + tid;
    const int q1 = q0 + 256;
    const int kbase = blockIdx.y * KC;

    float qA[16], qB[16];
    {
        const float4* qp0 = (const float4*)(g_q + q0 * DK);
        const float4* qp1 = (const float4*)(g_q + q1 * DK);
        #pragma unroll
        for (int i = 0; i < 4; i++) {
            float4 t = qp0[i];
            qA[4 * i + 0] = t.x; qA[4 * i + 1] = t.y; qA[4 * i + 2] = t.z; qA[4 * i + 3] = t.w;
            float4 u = qp1[i];
            qB[4 * i + 0] = u.x; qB[4 * i + 1] = u.y; qB[4 * i + 2] = u.z; qB[4 * i + 3] = u.w;
        }
    }

    float accA[16], accB[16];
    #pragma unroll
    for (int i = 0; i < 16; i++) { accA[i] = 0.f; accB[i] = 0.f; }
    float lA = 0.f, lB = 0.f;

    const float4* kp = (const float4*)(g_k + kbase * DK);
    const float4* vp = (const float4*)(g_v + kbase * DK);

    #pragma unroll 2
    for (int j = 0; j < KC; j++) {
        float kr[16];
        {
            float4 t0 = __ldg(kp + 4 * j + 0);
            float4 t1 = __ldg(kp + 4 * j + 1);
            float4 t2 = __ldg(kp + 4 * j + 2);
            float4 t3 = __ldg(kp + 4 * j + 3);
            kr[0] = t0.x; kr[1] = t0.y; kr[2]  = t0.z; kr[3]  = t0.w;
            kr[4] = t1.x; kr[5] = t1.y; kr[6]  = t1.z; kr[7]  = t1.w;
            kr[8] = t2.x; kr[9] = t2.y; kr[10] = t2.z; kr[11] = t2.w;
            kr[12] = t3.x; kr[13] = t3.y; kr[14] = t3.z; kr[15] = t3.w;
        }
        // two partial chains per query to shorten the dependency chain
        float dA0 = 0.f, dA1 = 0.f, dB0 = 0.f, dB1 = 0.f;
        #pragma unroll
        for (int c = 0; c < 8; c++) {
            dA0 = fmaf(qA[c], kr[c], dA0);
            dA1 = fmaf(qA[c + 8], kr[c + 8], dA1);
            dB0 = fmaf(qB[c], kr[c], dB0);
            dB1 = fmaf(qB[c + 8], kr[c + 8], dB1);
        }
        float pA = fast_exp2(dA0 + dA1);
        float pB = fast_exp2(dB0 + dB1);
        lA += pA;
        lB += pB;

        float vr[16];
        {
            float4 t0 = __ldg(vp + 4 * j + 0);
            float4 t1 = __ldg(vp + 4 * j + 1);
            float4 t2 = __ldg(vp + 4 * j + 2);
            float4 t3 = __ldg(vp + 4 * j + 3);
            vr[0] = t0.x; vr[1] = t0.y; vr[2]  = t0.z; vr[3]  = t0.w;
            vr[4] = t1.x; vr[5] = t1.y; vr[6]  = t1.z; vr[7]  = t1.w;
            vr[8] = t2.x; vr[9] = t2.y; vr[10] = t2.z; vr[11] = t2.w;
            vr[12] = t3.x; vr[13] = t3.y; vr[14] = t3.z; vr[15] = t3.w;
        }
        #pragma unroll
        for (int c = 0; c < 16; c++) {
            accA[c] = fmaf(pA, vr[c], accA[c]);
            accB[c] = fmaf(pB, vr[c], accB[c]);
        }
    }

    g_lp[blockIdx.y * NQ + q0] = lA;
    g_lp[blockIdx.y * NQ + q1] = lB;
    float4* ap0 = (float4*)(g_accp + (blockIdx.y * NQ + q0) * DK);
    float4* ap1 = (float4*)(g_accp + (blockIdx.y * NQ + q1) * DK);
    #pragma unroll
    for (int i = 0; i < 4; i++) {
        ap0[i] = make_float4(accA[4 * i], accA[4 * i + 1], accA[4 * i + 2], accA[4 * i + 3]);
        ap1[i] = make_float4(accB[4 * i], accB[4 * i + 1], accB[4 * i + 2], accB[4 * i + 3]);
    }
}

// ---------------------------------------------------------------------------
// Kernel 3: reduce partials across chunks, normalize, merge heads, and apply
// the 1x1x1 output projection.  One thread per spatial point.
// y[o][p] = ob[o] + sum_c ow[o][c] * (acc[q(c)][c%16] / l[q(c)])
// ---------------------------------------------------------------------------
__global__ __launch_bounds__(256) void out_kernel(
    const float* __restrict__ ow, const float* __restrict__ ob,
    float* __restrict__ y)
{
    __shared__ float4 wsm[COUT * 8];  // 64x32 floats
    const int tid = threadIdx.x;
    for (int i = tid; i < COUT * 8; i += 256) wsm[i] = ((const float4*)ow)[i];
    __syncthreads();

    const int p = blockIdx.x * 256 + tid;
    const int q0 = 2 * p, q1 = 2 * p + 1;

    float a0[16], a1[16];
    float l0 = 0.f, l1 = 0.f;
    #pragma unroll
    for (int i = 0; i < 16; i++) { a0[i] = 0.f; a1[i] = 0.f; }

    for (int ch = 0; ch < KCHUNKS; ch++) {
        l0 += g_lp[ch * NQ + q0];
        l1 += g_lp[ch * NQ + q1];
        const float4* ap0 = (const float4*)(g_accp + (ch * NQ + q0) * DK);
        const float4* ap1 = (const float4*)(g_accp + (ch * NQ + q1) * DK);
        #pragma unroll
        for (int i = 0; i < 4; i++) {
            float4 t = ap0[i];
            a0[4 * i + 0] += t.x; a0[4 * i + 1] += t.y;
            a0[4 * i + 2] += t.z; a0[4 * i + 3] += t.w;
            float4 u = ap1[i];
            a1[4 * i + 0] += u.x; a1[4 * i + 1] += u.y;
            a1[4 * i + 2] += u.z; a1[4 * i + 3] += u.w;
        }
    }

    const float inv0 = 1.0f / l0;
    const float inv1 = 1.0f / l1;
    float o32[32];
    #pragma unroll
    for (int i = 0; i < 16; i++) {
        o32[i] = a0[i] * inv0;        // head 0 -> channels [0,16)
        o32[16 + i] = a1[i] * inv1;   // head 1 -> channels [16,32)
    }

    for (int o = 0; o < COUT; o++) {
        float acc = __ldg(&ob[o]);
        #pragma unroll
        for (int c4 = 0; c4 < 8; c4++) {
            float4 w = wsm[o * 8 + c4];
            acc = fmaf(w.x, o32[4 * c4 + 0], acc);
            acc = fmaf(w.y, o32[4 * c4 + 1], acc);
            acc = fmaf(w.z, o32[4 * c4 + 2], acc);
            acc = fmaf(w.w, o32[4 * c4 + 3], acc);
        }
        y[o * NPTS + p] = acc;
    }
}

// ---------------------------------------------------------------------------
extern "C" void kernel_launch(void* const* d_in, const int* in_sizes, int n_in,
                              void* d_out, int out_size)
{
    const float* x  = (const float*)d_in[0];
    const float* qw = (const float*)d_in[1];
    const float* qb = (const float*)d_in[2];
    const float* kw = (const float*)d_in[3];
    const float* kb = (const float*)d_in[4];
    const float* vw = (const float*)d_in[5];
    const float* vb = (const float*)d_in[6];
    const float* ow = (const float*)d_in[7];
    const float* ob = (const float*)d_in[8];
    float* y = (float*)d_out;

    proj_kernel<<<NPTS / 256, 256>>>(x, qw, qb, kw, kb, vw, vb);
    dim3 grid(NQ / QBLOCK, KCHUNKS);
    attn_kernel<<<grid, 256>>>();
    out_kernel<<<NPTS / 256, 256>>>(ow, ob, y);
}

// round 4
// speedup vs baseline: 1.0017x; 1.0013x over previous
#include <cuda_runtime.h>

// Problem constants
#define NPTS 4096            // spatial points (16*16*16)
#define NQ   8192            // attention rows = NPTS * HEADS
#define CIN  64
#define CK   32              // qkv channels (= CV)
#define DK   16              // head dim (= dv)
#define COUT 64

// Attention tiling
#define KCHUNKS 64           // key-dimension splits
#define KC      128          // keys per chunk (KCHUNKS*KC = NQ)
#define QBLOCK  512          // queries per CTA (256 threads x 2 queries)

// Scratch (static device arrays; no allocation in kernel_launch)
__device__ float g_q[NQ * DK];            // pre-scaled by dk^-0.5 * log2(e)
__device__ float g_k[NQ * DK];
__device__ float g_v[NQ * DK];
__device__ float g_accp[KCHUNKS * NQ * DK];  // partial sum(exp * v)
__device__ float g_lp[KCHUNKS * NQ];         // partial sum(exp)

__device__ __forceinline__ float fast_exp2(float x) {
    float y;
    asm("ex2.approx.ftz.f32 %0, %1;" : "=f"(y) : "f"(x));
    return y;
}

// ---------------------------------------------------------------------------
// Kernel 1: QKV 1x1x1 conv projections.  One thread per spatial point.
// q[p][o] = sum_c x[c][p] * qw[o][c] + qb[o]   (o in [0,32)), same for k,v.
// Row layout: flattened [NQ][DK] == [NPTS][CK] (heads interleave naturally).
// Q is pre-scaled by dk^-0.5 * log2(e) so the attention loop uses ex2 directly.
// ---------------------------------------------------------------------------
__global__ __launch_bounds__(256) void proj_kernel(
    const float* __restrict__ x,
    const float* __restrict__ qw, const float* __restrict__ qb,
    const float* __restrict__ kw, const float* __restrict__ kb,
    const float* __restrict__ vw, const float* __restrict__ vb)
{
    __shared__ float4 wq[CK * 16], wk[CK * 16], wv[CK * 16];  // 32x64 floats each
    const int tid = threadIdx.x;
    for (int i = tid; i < CK * 16; i += 256) {
        wq[i] = ((const float4*)qw)[i];
        wk[i] = ((const float4*)kw)[i];
        wv[i] = ((const float4*)vw)[i];
    }
    __syncthreads();

    const int p = blockIdx.x * 256 + tid;

    float xr[CIN];
    #pragma unroll
    for (int c = 0; c < CIN; c++) xr[c] = __ldg(&x[c * NPTS + p]);

    const float QS = 0.25f * 1.4426950408889634f;  // dk^-0.5 * log2(e)

    for (int o = 0; o < CK; o++) {
        float aq = __ldg(&qb[o]);
        float ak = __ldg(&kb[o]);
        float av = __ldg(&vb[o]);
        #pragma unroll
        for (int c4 = 0; c4 < 16; c4++) {
            float4 a = wq[o * 16 + c4];
            aq = fmaf(a.x, xr[4 * c4 + 0], aq);
            aq = fmaf(a.y, xr[4 * c4 + 1], aq);
            aq = fmaf(a.z, xr[4 * c4 + 2], aq);
            aq = fmaf(a.w, xr[4 * c4 + 3], aq);
            float4 b = wk[o * 16 + c4];
            ak = fmaf(b.x, xr[4 * c4 + 0], ak);
            ak = fmaf(b.y, xr[4 * c4 + 1], ak);
            ak = fmaf(b.z, xr[4 * c4 + 2], ak);
            ak = fmaf(b.w, xr[4 * c4 + 3], ak);
            float4 cc = wv[o * 16 + c4];
            av = fmaf(cc.x, xr[4 * c4 + 0], av);
            av = fmaf(cc.y, xr[4 * c4 + 1], av);
            av = fmaf(cc.z, xr[4 * c4 + 2], av);
            av = fmaf(cc.w, xr[4 * c4 + 3], av);
        }
        g_q[p * CK + o] = aq * QS;
        g_k[p * CK + o] = ak;
        g_v[p * CK + o] = av;
    }
}

// ---------------------------------------------------------------------------
// Kernel 2: attention partials.  grid = (NQ/QBLOCK, KCHUNKS).
// Each thread owns 2 queries (registers: q[16]x2, acc[16]x2, l x2) and walks
// its CTA's key chunk.  No max-subtraction (logits are O(1), fp32-safe), so
// partials across chunks combine by plain addition -> deterministic.
// K/V rows are uniform-address loads (warp broadcast), amortized over 2 queries.
// ---------------------------------------------------------------------------
__global__ __launch_bounds__(256, 2) void attn_kernel()
{
    const int tid = threadIdx.x;
    const int q0 = blockIdx.x * QBLOCK + tid;
    const int q1 = q0 + 256;
    const int kbase = blockIdx.y * KC;

    float qA[16], qB[16];
    {
        const float4* qp0 = (const float4*)(g_q + q0 * DK);
        const float4* qp1 = (const float4*)(g_q + q1 * DK);
        #pragma unroll
        for (int i = 0; i < 4; i++) {
            float4 t = qp0[i];
            qA[4 * i + 0] = t.x; qA[4 * i + 1] = t.y; qA[4 * i + 2] = t.z; qA[4 * i + 3] = t.w;
            float4 u = qp1[i];
            qB[4 * i + 0] = u.x; qB[4 * i + 1] = u.y; qB[4 * i + 2] = u.z; qB[4 * i + 3] = u.w;
        }
    }

    float accA[16], accB[16];
    #pragma unroll
    for (int i = 0; i < 16; i++) { accA[i] = 0.f; accB[i] = 0.f; }
    float lA = 0.f, lB = 0.f;

    const float4* kp = (const float4*)(g_k + kbase * DK);
    const float4* vp = (const float4*)(g_v + kbase * DK);

    #pragma unroll 2
    for (int j = 0; j < KC; j++) {
        float kr[16];
        {
            float4 t0 = __ldg(kp + 4 * j + 0);
            float4 t1 = __ldg(kp + 4 * j + 1);
            float4 t2 = __ldg(kp + 4 * j + 2);
            float4 t3 = __ldg(kp + 4 * j + 3);
            kr[0] = t0.x; kr[1] = t0.y; kr[2]  = t0.z; kr[3]  = t0.w;
            kr[4] = t1.x; kr[5] = t1.y; kr[6]  = t1.z; kr[7]  = t1.w;
            kr[8] = t2.x; kr[9] = t2.y; kr[10] = t2.z; kr[11] = t2.w;
            kr[12] = t3.x; kr[13] = t3.y; kr[14] = t3.z; kr[15] = t3.w;
        }
        // two partial chains per query to shorten the dependency chain
        float dA0 = 0.f, dA1 = 0.f, dB0 = 0.f, dB1 = 0.f;
        #pragma unroll
        for (int c = 0; c < 8; c++) {
            dA0 = fmaf(qA[c], kr[c], dA0);
            dA1 = fmaf(qA[c + 8], kr[c + 8], dA1);
            dB0 = fmaf(qB[c], kr[c], dB0);
            dB1 = fmaf(qB[c + 8], kr[c + 8], dB1);
        }
        float pA = fast_exp2(dA0 + dA1);
        float pB = fast_exp2(dB0 + dB1);
        lA += pA;
        lB += pB;

        float vr[16];
        {
            float4 t0 = __ldg(vp + 4 * j + 0);
            float4 t1 = __ldg(vp + 4 * j + 1);
            float4 t2 = __ldg(vp + 4 * j + 2);
            float4 t3 = __ldg(vp + 4 * j + 3);
            vr[0] = t0.x; vr[1] = t0.y; vr[2]  = t0.z; vr[3]  = t0.w;
            vr[4] = t1.x; vr[5] = t1.y; vr[6]  = t1.z; vr[7]  = t1.w;
            vr[8] = t2.x; vr[9] = t2.y; vr[10] = t2.z; vr[11] = t2.w;
            vr[12] = t3.x; vr[13] = t3.y; vr[14] = t3.z; vr[15] = t3.w;
        }
        #pragma unroll
        for (int c = 0; c < 16; c++) {
            accA[c] = fmaf(pA, vr[c], accA[c]);
            accB[c] = fmaf(pB, vr[c], accB[c]);
        }
    }

    g_lp[blockIdx.y * NQ + q0] = lA;
    g_lp[blockIdx.y * NQ + q1] = lB;
    float4* ap0 = (float4*)(g_accp + (blockIdx.y * NQ + q0) * DK);
    float4* ap1 = (float4*)(g_accp + (blockIdx.y * NQ + q1) * DK);
    #pragma unroll
    for (int i = 0; i < 4; i++) {
        ap0[i] = make_float4(accA[4 * i], accA[4 * i + 1], accA[4 * i + 2], accA[4 * i + 3]);
        ap1[i] = make_float4(accB[4 * i], accB[4 * i + 1], accB[4 * i + 2], accB[4 * i + 3]);
    }
}

// ---------------------------------------------------------------------------
// Kernel 3: reduce partials across chunks, normalize, merge heads, and apply
// the 1x1x1 output projection.  One thread per spatial point.
// y[o][p] = ob[o] + sum_c ow[o][c] * (acc[q(c)][c%16] / l[q(c)])
// ---------------------------------------------------------------------------
__global__ __launch_bounds__(256) void out_kernel(
    const float* __restrict__ ow, const float* __restrict__ ob,
    float* __restrict__ y)
{
    __shared__ float4 wsm[COUT * 8];  // 64x32 floats
    const int tid = threadIdx.x;
    for (int i = tid; i < COUT * 8; i += 256) wsm[i] = ((const float4*)ow)[i];
    __syncthreads();

    const int p = blockIdx.x * 256 + tid;
    const int q0 = 2 * p, q1 = 2 * p + 1;

    float a0[16], a1[16];
    float l0 = 0.f, l1 = 0.f;
    #pragma unroll
    for (int i = 0; i < 16; i++) { a0[i] = 0.f; a1[i] = 0.f; }

    for (int ch = 0; ch < KCHUNKS; ch++) {
        l0 += g_lp[ch * NQ + q0];
        l1 += g_lp[ch * NQ + q1];
        const float4* ap0 = (const float4*)(g_accp + (ch * NQ + q0) * DK);
        const float4* ap1 = (const float4*)(g_accp + (ch * NQ + q1) * DK);
        #pragma unroll
        for (int i = 0; i < 4; i++) {
            float4 t = ap0[i];
            a0[4 * i + 0] += t.x; a0[4 * i + 1] += t.y;
            a0[4 * i + 2] += t.z; a0[4 * i + 3] += t.w;
            float4 u = ap1[i];
            a1[4 * i + 0] += u.x; a1[4 * i + 1] += u.y;
            a1[4 * i + 2] += u.z; a1[4 * i + 3] += u.w;
        }
    }

    const float inv0 = 1.0f / l0;
    const float inv1 = 1.0f / l1;
    float o32[32];
    #pragma unroll
    for (int i = 0; i < 16; i++) {
        o32[i] = a0[i] * inv0;        // head 0 -> channels [0,16)
        o32[16 + i] = a1[i] * inv1;   // head 1 -> channels [16,32)
    }

    for (int o = 0; o < COUT; o++) {
        float acc = __ldg(&ob[o]);
        #pragma unroll
        for (int c4 = 0; c4 < 8; c4++) {
            float4 w = wsm[o * 8 + c4];
            acc = fmaf(w.x, o32[4 * c4 + 0], acc);
            acc = fmaf(w.y, o32[4 * c4 + 1], acc);
            acc = fmaf(w.z, o32[4 * c4 + 2], acc);
            acc = fmaf(w.w, o32[4 * c4 + 3], acc);
        }
        y[o * NPTS + p] = acc;
    }
}

// ---------------------------------------------------------------------------
extern "C" void kernel_launch(void* const* d_in, const int* in_sizes, int n_in,
                              void* d_out, int out_size)
{
    const float* x  = (const float*)d_in[0];
    const float* qw = (const float*)d_in[1];
    const float* qb = (const float*)d_in[2];
    const float* kw = (const float*)d_in[3];
    const float* kb = (const float*)d_in[4];
    const float* vw = (const float*)d_in[5];
    const float* vb = (const float*)d_in[6];
    const float* ow = (const float*)d_in[7];
    const float* ob = (const float*)d_in[8];
    float* y = (float*)d_out;

    proj_kernel<<<NPTS / 256, 256>>>(x, qw, qb, kw, kb, vw, vb);
    dim3 grid(NQ / QBLOCK, KCHUNKS);
    attn_kernel<<<grid, 256>>>();
    out_kernel<<<NPTS / 256, 256>>>(ow, ob, y);
}